// round 2
// baseline (speedup 1.0000x reference)
#include <cuda_runtime.h>
#include <cstdint>
#include <math.h>

#define D_DIM   2048
#define E_DIM   64
#define TILE_T  64
#define BK      32
#define TOPK    2
#define PAD     2   // row pad (floats) for xs/ws: stride 34 -> LDS.64 conflict-free

__global__ __launch_bounds__(256, 2) void router_kernel(
    const float* __restrict__ x, const float* __restrict__ W,
    float* __restrict__ out, int T)
{
    __shared__ float xs[TILE_T][BK + PAD];
    __shared__ float ws[E_DIM][BK + PAD];
    __shared__ float lg[TILE_T][E_DIM + 1];

    const int tid = threadIdx.x;
    const int t0  = blockIdx.x * TILE_T;

    // microtile coords: token = r + 16*i, expert = c + 16*j  (i,j in 0..3)
    const int r = (tid >> 4) & 15;
    const int c = tid & 15;

    // global->smem load coords: one row-quad per thread, two float4 per tile
    const int lt = tid >> 2;          // 0..63 (token row / expert row)
    const int lk = (tid & 3) << 2;    // 0,4,8,12

    const float* xrow = x + (size_t)(t0 + lt) * D_DIM + lk;
    const float* wrow = W + (size_t)lt * D_DIM + lk;

    unsigned long long acc[4][4];
#pragma unroll
    for (int i = 0; i < 4; ++i)
#pragma unroll
        for (int j = 0; j < 4; ++j) acc[i][j] = 0ull;

    for (int k0 = 0; k0 < D_DIM; k0 += BK) {
        // prefetch before barrier
        float4 xv0 = *(const float4*)(xrow + k0);
        float4 xv1 = *(const float4*)(xrow + k0 + 16);
        float4 wv0 = *(const float4*)(wrow + k0);
        float4 wv1 = *(const float4*)(wrow + k0 + 16);

        __syncthreads();   // previous tile's reads done
        *(float2*)&xs[lt][lk +  0] = make_float2(xv0.x, xv0.y);
        *(float2*)&xs[lt][lk +  2] = make_float2(xv0.z, xv0.w);
        *(float2*)&xs[lt][lk + 16] = make_float2(xv1.x, xv1.y);
        *(float2*)&xs[lt][lk + 18] = make_float2(xv1.z, xv1.w);
        *(float2*)&ws[lt][lk +  0] = make_float2(wv0.x, wv0.y);
        *(float2*)&ws[lt][lk +  2] = make_float2(wv0.z, wv0.w);
        *(float2*)&ws[lt][lk + 16] = make_float2(wv1.x, wv1.y);
        *(float2*)&ws[lt][lk + 18] = make_float2(wv1.z, wv1.w);
        __syncthreads();

#pragma unroll
        for (int kk = 0; kk < BK; kk += 2) {
            unsigned long long a[4], b[4];
#pragma unroll
            for (int i = 0; i < 4; ++i)
                a[i] = *(const unsigned long long*)&xs[r + 16 * i][kk];
#pragma unroll
            for (int j = 0; j < 4; ++j)
                b[j] = *(const unsigned long long*)&ws[c + 16 * j][kk];
#pragma unroll
            for (int i = 0; i < 4; ++i)
#pragma unroll
                for (int j = 0; j < 4; ++j)
                    asm("fma.rn.f32x2 %0, %1, %2, %0;"
                        : "+l"(acc[i][j]) : "l"(a[i]), "l"(b[j]));
        }
    }

    // reduce packed pairs -> logits in smem
#pragma unroll
    for (int i = 0; i < 4; ++i)
#pragma unroll
        for (int j = 0; j < 4; ++j) {
            float lo, hi;
            asm("mov.b64 {%0,%1}, %2;" : "=f"(lo), "=f"(hi) : "l"(acc[i][j]));
            lg[r + 16 * i][c + 16 * j] = lo + hi;
        }
    __syncthreads();

    // epilogue: one thread per token
    if (tid < TILE_T) {
        const int t = t0 + tid;

        // top-2 on logits (softmax is monotonic); '>' keeps lower index on ties,
        // matching jax.lax.top_k tie-break.
        float m1 = -INFINITY, m2 = -INFINITY;
        int i1 = 0, i2 = 0;
#pragma unroll 8
        for (int e = 0; e < E_DIM; ++e) {
            float v = lg[tid][e];
            if (v > m1)      { m2 = m1; i2 = i1; m1 = v; i1 = e; }
            else if (v > m2) { m2 = v; i2 = e; }
        }
        float s = 0.f;
#pragma unroll 8
        for (int e = 0; e < E_DIM; ++e) s += expf(lg[tid][e] - m1);
        const float inv  = 1.0f / s;
        const float p1   = inv;                   // expf(0) * inv
        const float p2   = expf(m2 - m1) * inv;
        const float rinv = 1.0f / (p1 + p2);

        const size_t TT = (size_t)T;
        float* mask_o = out + (size_t)t * E_DIM;
        float* idx_o  = out + TT * E_DIM + (size_t)t * TOPK;
        float* rp_o   = out + TT * (E_DIM + TOPK) + (size_t)t * E_DIM;
        float* p_o    = out + TT * (2 * E_DIM + TOPK) + (size_t)t * E_DIM;

        idx_o[0] = (float)i1;
        idx_o[1] = (float)i2;

#pragma unroll 4
        for (int e = 0; e < E_DIM; e += 4) {
            float4 pv, mv, rv;
            float p;
            p = expf(lg[tid][e + 0] - m1) * inv;
            mv.x = (e + 0 == i1 || e + 0 == i2) ? 1.0f : 0.0f;
            pv.x = p; rv.x = mv.x * p * rinv;
            p = expf(lg[tid][e + 1] - m1) * inv;
            mv.y = (e + 1 == i1 || e + 1 == i2) ? 1.0f : 0.0f;
            pv.y = p; rv.y = mv.y * p * rinv;
            p = expf(lg[tid][e + 2] - m1) * inv;
            mv.z = (e + 2 == i1 || e + 2 == i2) ? 1.0f : 0.0f;
            pv.z = p; rv.z = mv.z * p * rinv;
            p = expf(lg[tid][e + 3] - m1) * inv;
            mv.w = (e + 3 == i1 || e + 3 == i2) ? 1.0f : 0.0f;
            pv.w = p; rv.w = mv.w * p * rinv;

            *(float4*)(mask_o + e) = mv;
            *(float4*)(p_o    + e) = pv;
            *(float4*)(rp_o   + e) = rv;
        }
    }
}

extern "C" void kernel_launch(void* const* d_in, const int* in_sizes, int n_in,
                              void* d_out, int out_size)
{
    const float* x = (const float*)d_in[0];
    const float* W = (const float*)d_in[1];
    float* out = (float*)d_out;

    const int T = in_sizes[0] / D_DIM;   // 16384
    const int grid = T / TILE_T;         // 256

    router_kernel<<<grid, 256>>>(x, W, out, T);
}